// round 2
// baseline (speedup 1.0000x reference)
#include <cuda_runtime.h>
#include <math.h>

// Problem constants (fixed by the reference setup)
#define N_BATCH 2
#define LQ      16384
#define CDIM    256
#define NH      8
#define NL      4
#define NP      4
#define DH      32         // head dim
#define LIN     21760      // 128^2 + 64^2 + 32^2 + 16^2
#define NGROUP  (N_BATCH*LQ*NH)   // softmax groups

// Scratch (device globals; allocation is forbidden)
__device__ float g_value  [N_BATCH*LIN*CDIM];   // projected values   [N, Lin, M*D]
__device__ float g_off    [N_BATCH*LQ*CDIM];    // sampling offsets   [N, Lq, M*L*P*2]
__device__ float g_attn   [N_BATCH*LQ*NH*NL*NP];// attn (post-softmax)[N, Lq, M*16]
__device__ float g_sampled[N_BATCH*LQ*CDIM];    // sampled output     [N, Lq, M*D]

// ---------------------------------------------------------------------------
// Tiled fp32 GEMM with bias: C[M,N] = A[M,K] @ B[K,N] + bias[N]
// BM=BN=64, BK=16, 256 threads, 4x4 microtile. All dims divide tiles exactly.
// ---------------------------------------------------------------------------
#define BM 64
#define BN 64
#define BK 16

__global__ __launch_bounds__(256) void gemm_bias_kernel(
    const float* __restrict__ A, const float* __restrict__ B,
    const float* __restrict__ bias, float* __restrict__ C,
    int M, int N, int K)
{
    __shared__ float As[BK][BM + 4];   // stored transposed: As[k][m]
    __shared__ float Bs[BK][BN + 4];

    const int bm = blockIdx.y * BM;
    const int bn = blockIdx.x * BN;
    const int tid = threadIdx.x;
    const int tr = tid >> 4;          // 0..15  (row group)
    const int tc = tid & 15;          // 0..15  (col group)

    // A-tile loader: 64 rows x 16 cols, one float4 per thread
    const int arow = tid >> 2;            // 0..63
    const int acol = (tid & 3) * 4;       // 0,4,8,12
    // B-tile loader: 16 rows x 64 cols, one float4 per thread
    const int brow = tid >> 4;            // 0..15
    const int bcol = (tid & 15) * 4;      // 0..60

    const float* Aptr = A + (size_t)(bm + arow) * K + acol;
    const float* Bptr = B + (size_t)brow * N + bn + bcol;

    float acc[4][4];
    #pragma unroll
    for (int i = 0; i < 4; i++)
        #pragma unroll
        for (int j = 0; j < 4; j++) acc[i][j] = 0.f;

    for (int k0 = 0; k0 < K; k0 += BK) {
        float4 av = *(const float4*)(Aptr + k0);
        As[acol + 0][arow] = av.x;
        As[acol + 1][arow] = av.y;
        As[acol + 2][arow] = av.z;
        As[acol + 3][arow] = av.w;
        *(float4*)&Bs[brow][bcol] = *(const float4*)(Bptr + (size_t)k0 * N);
        __syncthreads();

        #pragma unroll
        for (int k = 0; k < BK; k++) {
            float4 a = *(const float4*)&As[k][tr * 4];
            float4 b = *(const float4*)&Bs[k][tc * 4];
            float ar[4] = {a.x, a.y, a.z, a.w};
            float br[4] = {b.x, b.y, b.z, b.w};
            #pragma unroll
            for (int i = 0; i < 4; i++)
                #pragma unroll
                for (int j = 0; j < 4; j++)
                    acc[i][j] = fmaf(ar[i], br[j], acc[i][j]);
        }
        __syncthreads();
    }

    const int colbase = bn + tc * 4;
    float4 bv = *(const float4*)&bias[colbase];
    float bb[4] = {bv.x, bv.y, bv.z, bv.w};
    #pragma unroll
    for (int i = 0; i < 4; i++) {
        const int row = bm + tr * 4 + i;
        float4 o;
        o.x = acc[i][0] + bb[0];
        o.y = acc[i][1] + bb[1];
        o.z = acc[i][2] + bb[2];
        o.w = acc[i][3] + bb[3];
        *(float4*)&C[(size_t)row * N + colbase] = o;
    }
}

// ---------------------------------------------------------------------------
// Softmax over groups of 16 (one thread per (n,q,head))
// ---------------------------------------------------------------------------
__global__ void softmax16_kernel(float* __restrict__ attn)
{
    int i = blockIdx.x * blockDim.x + threadIdx.x;
    if (i >= NGROUP) return;
    float* p = attn + (size_t)i * 16;
    float4 v0 = *(float4*)(p + 0);
    float4 v1 = *(float4*)(p + 4);
    float4 v2 = *(float4*)(p + 8);
    float4 v3 = *(float4*)(p + 12);
    float vals[16] = {v0.x,v0.y,v0.z,v0.w, v1.x,v1.y,v1.z,v1.w,
                      v2.x,v2.y,v2.z,v2.w, v3.x,v3.y,v3.z,v3.w};
    float mx = vals[0];
    #pragma unroll
    for (int k = 1; k < 16; k++) mx = fmaxf(mx, vals[k]);
    float s = 0.f;
    #pragma unroll
    for (int k = 0; k < 16; k++) { vals[k] = expf(vals[k] - mx); s += vals[k]; }
    float inv = 1.f / s;
    #pragma unroll
    for (int k = 0; k < 16; k++) vals[k] *= inv;
    v0 = make_float4(vals[0],vals[1],vals[2],vals[3]);
    v1 = make_float4(vals[4],vals[5],vals[6],vals[7]);
    v2 = make_float4(vals[8],vals[9],vals[10],vals[11]);
    v3 = make_float4(vals[12],vals[13],vals[14],vals[15]);
    *(float4*)(p + 0)  = v0;
    *(float4*)(p + 4)  = v1;
    *(float4*)(p + 8)  = v2;
    *(float4*)(p + 12) = v3;
}

// ---------------------------------------------------------------------------
// Deformable sampling: warp per (n, q, head); lane = head-dim channel d.
//
// NOTE on weight pairing: the reference orders sampled values p-major
// (index p*L+l) but attention weights l-major (index l*P+p) before the
// elementwise product, so the sample taken at (level l, point p) is
// weighted by attn[p*4 + l] (transposed (l,p) pairing).
// ---------------------------------------------------------------------------
__global__ __launch_bounds__(256) void sample_kernel()
{
    const int wg   = (blockIdx.x * 256 + threadIdx.x) >> 5;   // global warp id
    const int lane = threadIdx.x & 31;
    const int m = wg & 7;
    const int q = (wg >> 3) & (LQ - 1);
    const int n = wg >> 17;

    const float refx = ((q & 127) + 0.5f) * (1.0f / 128.0f);
    const float refy = ((q >> 7)  + 0.5f) * (1.0f / 128.0f);

    const float* offp  = g_off  + (size_t)(n * LQ + q) * CDIM + m * (NL * NP * 2);
    const float* attnp = g_attn + (size_t)(n * LQ + q) * (NH * NL * NP) + m * (NL * NP);

    float acc = 0.f;
    int start = 0;
    #pragma unroll
    for (int l = 0; l < NL; l++) {
        const int W = 128 >> l;            // square levels: H == W
        const float fW = (float)W;
        const float* vbase = g_value + ((size_t)(n * LIN + start)) * CDIM + m * DH + lane;

        #pragma unroll
        for (int p = 0; p < NP; p++) {
            const int pi = l * NP + p;
            const float ox = offp[pi * 2 + 0];
            const float oy = offp[pi * 2 + 1];
            const float a  = attnp[p * NP + l];   // transposed (l,p) pairing, see note

            // x = loc_x*W - 0.5 (align_corners=False), zero padding
            const float x = refx * fW + ox - 0.5f;
            const float y = refy * fW + oy - 0.5f;
            const float xf = floorf(x), yf = floorf(y);
            const int x0 = (int)xf, y0 = (int)yf;
            const float wx1 = x - xf, wy1 = y - yf;
            const float wx0 = 1.f - wx1, wy0 = 1.f - wy1;

            const bool vx0 = (x0 >= 0) && (x0 < W);
            const bool vx1 = (x0 >= -1) && (x0 < W - 1);
            const bool vy0 = (y0 >= 0) && (y0 < W);
            const bool vy1 = (y0 >= -1) && (y0 < W - 1);

            const int base0 = y0 * W + x0;
            float v00 = (vy0 && vx0) ? vbase[(size_t)(base0)         * CDIM] : 0.f;
            float v01 = (vy0 && vx1) ? vbase[(size_t)(base0 + 1)     * CDIM] : 0.f;
            float v10 = (vy1 && vx0) ? vbase[(size_t)(base0 + W)     * CDIM] : 0.f;
            float v11 = (vy1 && vx1) ? vbase[(size_t)(base0 + W + 1) * CDIM] : 0.f;

            acc = fmaf(a, wy0 * (wx0 * v00 + wx1 * v01) +
                          wy1 * (wx0 * v10 + wx1 * v11), acc);
        }
        start += W * W;
    }
    g_sampled[(size_t)(n * LQ + q) * CDIM + m * DH + lane] = acc;
}

// ---------------------------------------------------------------------------
// kernel_launch
// ---------------------------------------------------------------------------
extern "C" void kernel_launch(void* const* d_in, const int* in_sizes, int n_in,
                              void* d_out, int out_size)
{
    const float* query         = (const float*)d_in[0];
    // d_in[1] reference_points: unused by the reference forward
    const float* input_flatten = (const float*)d_in[2];
    // d_in[3] spatial_shapes, d_in[4] level_start_index: constants, hardcoded
    const float* W_off  = (const float*)d_in[5];
    const float* b_off  = (const float*)d_in[6];
    const float* W_attn = (const float*)d_in[7];
    const float* b_attn = (const float*)d_in[8];
    const float* W_val  = (const float*)d_in[9];
    const float* b_val  = (const float*)d_in[10];
    const float* W_out  = (const float*)d_in[11];
    const float* b_out  = (const float*)d_in[12];
    float* out = (float*)d_out;

    float *p_value, *p_off, *p_attn, *p_sampled;
    cudaGetSymbolAddress((void**)&p_value,   g_value);
    cudaGetSymbolAddress((void**)&p_off,     g_off);
    cudaGetSymbolAddress((void**)&p_attn,    g_attn);
    cudaGetSymbolAddress((void**)&p_sampled, g_sampled);

    // 1) value projection: [2*21760, 256] = input_flatten @ W_val + b_val
    gemm_bias_kernel<<<dim3(CDIM / BN, (N_BATCH * LIN) / BM), 256>>>(
        input_flatten, W_val, b_val, p_value, N_BATCH * LIN, CDIM, CDIM);

    // 2) offset projection: [2*16384, 256] = query @ W_off + b_off
    gemm_bias_kernel<<<dim3(CDIM / BN, (N_BATCH * LQ) / BM), 256>>>(
        query, W_off, b_off, p_off, N_BATCH * LQ, CDIM, CDIM);

    // 3) attention logits: [2*16384, 128] = query @ W_attn + b_attn
    gemm_bias_kernel<<<dim3(128 / BN, (N_BATCH * LQ) / BM), 256>>>(
        query, W_attn, b_attn, p_attn, N_BATCH * LQ, 128, CDIM);

    // 4) softmax over 16 points per (n,q,head)
    softmax16_kernel<<<(NGROUP + 255) / 256, 256>>>(p_attn);

    // 5) deformable bilinear sampling + attention-weighted sum
    sample_kernel<<<(N_BATCH * LQ * NH) / 8, 256>>>();

    // 6) output projection: out = sampled @ W_out + b_out
    gemm_bias_kernel<<<dim3(CDIM / BN, (N_BATCH * LQ) / BM), 256>>>(
        p_sampled, W_out, b_out, out, N_BATCH * LQ, CDIM, CDIM);
}

// round 5
// speedup vs baseline: 1.4187x; 1.4187x over previous
#include <cuda_runtime.h>
#include <cuda_bf16.h>
#include <cstdint>
#include <math.h>

// Problem constants (fixed by the reference setup)
#define N_BATCH 2
#define LQ      16384
#define CDIM    256
#define NH      8
#define NL      4
#define NP      4
#define DH      32
#define LIN     21760
#define NGROUP  (N_BATCH*LQ*NH)

// Scratch (device globals; allocation is forbidden)
__device__ float g_value  [N_BATCH*LIN*CDIM];
__device__ float g_off    [N_BATCH*LQ*CDIM];
__device__ float g_attn   [N_BATCH*LQ*NH*NL*NP];
__device__ float g_sampled[N_BATCH*LQ*CDIM];
// Pre-transposed weights, bf16 hi/lo split: [N, K=256] row-major
__device__ __nv_bfloat16 g_wval_hi [CDIM*CDIM], g_wval_lo [CDIM*CDIM];
__device__ __nv_bfloat16 g_woff_hi [CDIM*CDIM], g_woff_lo [CDIM*CDIM];
__device__ __nv_bfloat16 g_wattn_hi[128*CDIM],  g_wattn_lo[128*CDIM];
__device__ __nv_bfloat16 g_wout_hi [CDIM*CDIM], g_wout_lo [CDIM*CDIM];

// ---------------------------------------------------------------------------
// Warp MMA helpers (standard PTX, sm_80+; compiles for plain sm_103)
// ---------------------------------------------------------------------------
__device__ __forceinline__ uint32_t smem_u32(const void* p) {
    uint32_t a;
    asm("{ .reg .u64 t; cvta.to.shared.u64 t, %1; cvt.u32.u64 %0, t; }"
        : "=r"(a) : "l"(p));
    return a;
}

__device__ __forceinline__ void ldsm4(uint32_t* r, uint32_t addr) {
    asm volatile("ldmatrix.sync.aligned.m8n8.x4.shared.b16 {%0,%1,%2,%3}, [%4];"
                 : "=r"(r[0]), "=r"(r[1]), "=r"(r[2]), "=r"(r[3]) : "r"(addr));
}

__device__ __forceinline__ void mma16816(float* d, const uint32_t* a, const uint32_t* b) {
    asm volatile(
        "mma.sync.aligned.m16n8k16.row.col.f32.bf16.bf16.f32 "
        "{%0,%1,%2,%3}, {%4,%5,%6,%7}, {%8,%9}, {%0,%1,%2,%3};"
        : "+f"(d[0]), "+f"(d[1]), "+f"(d[2]), "+f"(d[3])
        : "r"(a[0]), "r"(a[1]), "r"(a[2]), "r"(a[3]), "r"(b[0]), "r"(b[1]));
}

// ---------------------------------------------------------------------------
// Weight transpose + bf16 hi/lo split: W[K=256, N] -> Wt_hi/lo[N, 256]
// ---------------------------------------------------------------------------
__global__ void transpose_w_kernel(const float* __restrict__ W,
                                   __nv_bfloat16* __restrict__ hi,
                                   __nv_bfloat16* __restrict__ lo, int N)
{
    int idx = blockIdx.x * 256 + threadIdx.x;
    if (idx >= 256 * N) return;
    int k = idx / N, n = idx % N;
    float w = W[idx];
    __nv_bfloat16 h = __float2bfloat16(w);
    float r = w - __bfloat162float(h);
    hi[n * 256 + k] = h;
    lo[n * 256 + k] = __float2bfloat16(r);
}

// ---------------------------------------------------------------------------
// HMMA GEMM, bf16x3 split: C[M, N] = A[M,256] @ Bt[N,256]^T + bias
// CTA tile 128x128, BK=32, 8 warps in 4(m) x 2(n), warp tile 32x64.
// A is fp32 (converted to hi/lo on the fly); Bt is pre-split bf16 hi/lo.
// smem rows padded to 80B -> ldmatrix conflict-free.
// ---------------------------------------------------------------------------
#define GK       256
#define GBK      32
#define ASTRIDEB 80     // bytes per 32-elem bf16 row (64B data + 16B pad)

__global__ __launch_bounds__(256) void gemm_mma_kernel(
    const float* __restrict__ A,
    const __nv_bfloat16* __restrict__ Bt_hi,
    const __nv_bfloat16* __restrict__ Bt_lo,
    const float* __restrict__ bias,
    float* __restrict__ C, int ldc)
{
    __shared__ __align__(16) char sm[4 * 128 * ASTRIDEB];   // 40960B
    const int AH = 0;
    const int AL = 128 * ASTRIDEB;
    const int BH = 2 * 128 * ASTRIDEB;
    const int BL = 3 * 128 * ASTRIDEB;

    const uint32_t sb = smem_u32(sm);
    const int tid  = threadIdx.x;
    const int wid  = tid >> 5, lane = tid & 31;
    const int wm   = wid & 3,  wn   = wid >> 2;
    const int m0   = blockIdx.x * 128;
    const int n0   = blockIdx.y * 128;

    // fill mapping: thread -> (row, k-half)
    const int frow = tid >> 1;
    const int fkh  = (tid & 1) * 16;

    float acc[2][8][4];
    #pragma unroll
    for (int i = 0; i < 2; i++)
        #pragma unroll
        for (int j = 0; j < 8; j++)
            #pragma unroll
            for (int v = 0; v < 4; v++) acc[i][j][v] = 0.f;

    // ldmatrix source addresses (fixed per thread; add kk*2 per k-step)
    // A tiles: row = wm*32 + mt*16 + (lane&15), col = (lane>>4)*8
    uint32_t a_addr[2];
    #pragma unroll
    for (int mt = 0; mt < 2; mt++)
        a_addr[mt] = sb + (wm * 32 + mt * 16 + (lane & 15)) * ASTRIDEB
                        + ((lane >> 4) * 8) * 2;
    // B tiles: row(n) = wn*64 + bt*16 + (lane>>4)*8 + (lane&7), col(k) = ((lane>>3)&1)*8
    uint32_t b_addr[4];
    #pragma unroll
    for (int bt = 0; bt < 4; bt++)
        b_addr[bt] = sb + (wn * 64 + bt * 16 + ((lane >> 4) * 8) + (lane & 7)) * ASTRIDEB
                        + (((lane >> 3) & 1) * 8) * 2;

    for (int k0 = 0; k0 < GK; k0 += GBK) {
        // ---- A: 128x32 fp32 -> bf16 hi/lo (16 elems/thread)
        {
            const float4* src = (const float4*)(A + (size_t)(m0 + frow) * GK + k0 + fkh);
            float v[16];
            #pragma unroll
            for (int i = 0; i < 4; i++) {
                float4 f = src[i];
                v[i*4+0] = f.x; v[i*4+1] = f.y; v[i*4+2] = f.z; v[i*4+3] = f.w;
            }
            __nv_bfloat16 h[16], l[16];
            #pragma unroll
            for (int i = 0; i < 16; i++) {
                h[i] = __float2bfloat16(v[i]);
                l[i] = __float2bfloat16(v[i] - __bfloat162float(h[i]));
            }
            char* dh = sm + AH + frow * ASTRIDEB + fkh * 2;
            char* dl = sm + AL + frow * ASTRIDEB + fkh * 2;
            ((uint4*)dh)[0] = ((uint4*)h)[0];  ((uint4*)dh)[1] = ((uint4*)h)[1];
            ((uint4*)dl)[0] = ((uint4*)l)[0];  ((uint4*)dl)[1] = ((uint4*)l)[1];
        }
        // ---- B: 128x32 bf16 hi/lo copy
        {
            const uint4* sh = (const uint4*)(Bt_hi + (size_t)(n0 + frow) * GK + k0 + fkh);
            const uint4* sl = (const uint4*)(Bt_lo + (size_t)(n0 + frow) * GK + k0 + fkh);
            char* dh = sm + BH + frow * ASTRIDEB + fkh * 2;
            char* dl = sm + BL + frow * ASTRIDEB + fkh * 2;
            ((uint4*)dh)[0] = sh[0];  ((uint4*)dh)[1] = sh[1];
            ((uint4*)dl)[0] = sl[0];  ((uint4*)dl)[1] = sl[1];
        }
        __syncthreads();

        #pragma unroll
        for (int kk = 0; kk < GBK; kk += 16) {
            const uint32_t ko = kk * 2;   // byte offset for this k-step
            uint32_t ah[2][4], al[2][4];
            #pragma unroll
            for (int mt = 0; mt < 2; mt++) {
                ldsm4(ah[mt], a_addr[mt] + AH + ko);   // AH==0, kept for clarity
                ldsm4(al[mt], a_addr[mt] + AL + ko);
            }
            #pragma unroll
            for (int bt = 0; bt < 4; bt++) {
                uint32_t bh[4], bl[4];
                ldsm4(bh, b_addr[bt] + BH + ko);
                ldsm4(bl, b_addr[bt] + BL + ko);
                #pragma unroll
                for (int mt = 0; mt < 2; mt++) {
                    float* d0 = acc[mt][bt * 2 + 0];
                    float* d1 = acc[mt][bt * 2 + 1];
                    mma16816(d0, ah[mt], bh + 0);
                    mma16816(d0, ah[mt], bl + 0);
                    mma16816(d0, al[mt], bh + 0);
                    mma16816(d1, ah[mt], bh + 2);
                    mma16816(d1, ah[mt], bl + 2);
                    mma16816(d1, al[mt], bh + 2);
                }
            }
        }
        __syncthreads();
    }

    // ---- epilogue: fragment -> global, bias added
    const int r_in = lane >> 2;            // 0..7
    const int c_in = (lane & 3) * 2;       // 0,2,4,6
    #pragma unroll
    for (int mt = 0; mt < 2; mt++) {
        const int rbase = m0 + wm * 32 + mt * 16 + r_in;
        #pragma unroll
        for (int nf = 0; nf < 8; nf++) {
            const int col = n0 + wn * 64 + nf * 8 + c_in;
            const float b0 = bias[col], b1 = bias[col + 1];
            float* d = acc[mt][nf];
            float2 o0 = make_float2(d[0] + b0, d[1] + b1);
            float2 o1 = make_float2(d[2] + b0, d[3] + b1);
            *(float2*)(C + (size_t)rbase       * ldc + col) = o0;
            *(float2*)(C + (size_t)(rbase + 8) * ldc + col) = o1;
        }
    }
}

// ---------------------------------------------------------------------------
// Softmax over groups of 16 (one thread per (n,q,head))
// ---------------------------------------------------------------------------
__global__ void softmax16_kernel(float* __restrict__ attn)
{
    int i = blockIdx.x * blockDim.x + threadIdx.x;
    if (i >= NGROUP) return;
    float* p = attn + (size_t)i * 16;
    float4 v0 = *(float4*)(p + 0);
    float4 v1 = *(float4*)(p + 4);
    float4 v2 = *(float4*)(p + 8);
    float4 v3 = *(float4*)(p + 12);
    float vals[16] = {v0.x,v0.y,v0.z,v0.w, v1.x,v1.y,v1.z,v1.w,
                      v2.x,v2.y,v2.z,v2.w, v3.x,v3.y,v3.z,v3.w};
    float mx = vals[0];
    #pragma unroll
    for (int k = 1; k < 16; k++) mx = fmaxf(mx, vals[k]);
    float s = 0.f;
    #pragma unroll
    for (int k = 0; k < 16; k++) { vals[k] = expf(vals[k] - mx); s += vals[k]; }
    float inv = 1.f / s;
    #pragma unroll
    for (int k = 0; k < 16; k++) vals[k] *= inv;
    *(float4*)(p + 0)  = make_float4(vals[0],vals[1],vals[2],vals[3]);
    *(float4*)(p + 4)  = make_float4(vals[4],vals[5],vals[6],vals[7]);
    *(float4*)(p + 8)  = make_float4(vals[8],vals[9],vals[10],vals[11]);
    *(float4*)(p + 12) = make_float4(vals[12],vals[13],vals[14],vals[15]);
}

// ---------------------------------------------------------------------------
// Deformable sampling (weight pairing: sample(l,p) uses attn[p*4+l] — the
// reference pairs p-major values with l-major weights)
// ---------------------------------------------------------------------------
__global__ __launch_bounds__(256) void sample_kernel()
{
    const int wg   = (blockIdx.x * 256 + threadIdx.x) >> 5;
    const int lane = threadIdx.x & 31;
    const int m = wg & 7;
    const int q = (wg >> 3) & (LQ - 1);
    const int n = wg >> 17;

    const float refx = ((q & 127) + 0.5f) * (1.0f / 128.0f);
    const float refy = ((q >> 7)  + 0.5f) * (1.0f / 128.0f);

    const float* offp  = g_off  + (size_t)(n * LQ + q) * CDIM + m * (NL * NP * 2);
    const float* attnp = g_attn + (size_t)(n * LQ + q) * (NH * NL * NP) + m * (NL * NP);

    float acc = 0.f;
    int start = 0;
    #pragma unroll
    for (int l = 0; l < NL; l++) {
        const int W = 128 >> l;
        const float fW = (float)W;
        const float* vbase = g_value + ((size_t)(n * LIN + start)) * CDIM + m * DH + lane;

        #pragma unroll
        for (int p = 0; p < NP; p++) {
            const int pi = l * NP + p;
            const float ox = offp[pi * 2 + 0];
            const float oy = offp[pi * 2 + 1];
            const float a  = attnp[p * NP + l];

            const float x = refx * fW + ox - 0.5f;
            const float y = refy * fW + oy - 0.5f;
            const float xf = floorf(x), yf = floorf(y);
            const int x0 = (int)xf, y0 = (int)yf;
            const float wx1 = x - xf, wy1 = y - yf;
            const float wx0 = 1.f - wx1, wy0 = 1.f - wy1;

            const bool vx0 = (x0 >= 0) && (x0 < W);
            const bool vx1 = (x0 >= -1) && (x0 < W - 1);
            const bool vy0 = (y0 >= 0) && (y0 < W);
            const bool vy1 = (y0 >= -1) && (y0 < W - 1);

            const int base0 = y0 * W + x0;
            float v00 = (vy0 && vx0) ? vbase[(size_t)(base0)         * CDIM] : 0.f;
            float v01 = (vy0 && vx1) ? vbase[(size_t)(base0 + 1)     * CDIM] : 0.f;
            float v10 = (vy1 && vx0) ? vbase[(size_t)(base0 + W)     * CDIM] : 0.f;
            float v11 = (vy1 && vx1) ? vbase[(size_t)(base0 + W + 1) * CDIM] : 0.f;

            acc = fmaf(a, wy0 * (wx0 * v00 + wx1 * v01) +
                          wy1 * (wx0 * v10 + wx1 * v11), acc);
        }
        start += W * W;
    }
    g_sampled[(size_t)(n * LQ + q) * CDIM + m * DH + lane] = acc;
}

// ---------------------------------------------------------------------------
// kernel_launch
// ---------------------------------------------------------------------------
extern "C" void kernel_launch(void* const* d_in, const int* in_sizes, int n_in,
                              void* d_out, int out_size)
{
    const float* query         = (const float*)d_in[0];
    const float* input_flatten = (const float*)d_in[2];
    const float* W_off  = (const float*)d_in[5];
    const float* b_off  = (const float*)d_in[6];
    const float* W_attn = (const float*)d_in[7];
    const float* b_attn = (const float*)d_in[8];
    const float* W_val  = (const float*)d_in[9];
    const float* b_val  = (const float*)d_in[10];
    const float* W_out  = (const float*)d_in[11];
    const float* b_out  = (const float*)d_in[12];
    float* out = (float*)d_out;

    float *p_value, *p_off, *p_attn, *p_sampled;
    cudaGetSymbolAddress((void**)&p_value,   g_value);
    cudaGetSymbolAddress((void**)&p_off,     g_off);
    cudaGetSymbolAddress((void**)&p_attn,    g_attn);
    cudaGetSymbolAddress((void**)&p_sampled, g_sampled);
    __nv_bfloat16 *wv_h, *wv_l, *wo_h, *wo_l, *wa_h, *wa_l, *wu_h, *wu_l;
    cudaGetSymbolAddress((void**)&wv_h, g_wval_hi);  cudaGetSymbolAddress((void**)&wv_l, g_wval_lo);
    cudaGetSymbolAddress((void**)&wo_h, g_woff_hi);  cudaGetSymbolAddress((void**)&wo_l, g_woff_lo);
    cudaGetSymbolAddress((void**)&wa_h, g_wattn_hi); cudaGetSymbolAddress((void**)&wa_l, g_wattn_lo);
    cudaGetSymbolAddress((void**)&wu_h, g_wout_hi);  cudaGetSymbolAddress((void**)&wu_l, g_wout_lo);

    // 0) weight transpose + split (tiny)
    transpose_w_kernel<<<(256 * 256 + 255) / 256, 256>>>(W_val,  wv_h, wv_l, 256);
    transpose_w_kernel<<<(256 * 256 + 255) / 256, 256>>>(W_off,  wo_h, wo_l, 256);
    transpose_w_kernel<<<(256 * 128 + 255) / 256, 256>>>(W_attn, wa_h, wa_l, 128);
    transpose_w_kernel<<<(256 * 256 + 255) / 256, 256>>>(W_out,  wu_h, wu_l, 256);

    // 1) value projection [43520, 256]
    gemm_mma_kernel<<<dim3((N_BATCH * LIN) / 128, 2), 256>>>(
        input_flatten, wv_h, wv_l, b_val, p_value, 256);
    // 2) offset projection [32768, 256]
    gemm_mma_kernel<<<dim3((N_BATCH * LQ) / 128, 2), 256>>>(
        query, wo_h, wo_l, b_off, p_off, 256);
    // 3) attention logits [32768, 128]
    gemm_mma_kernel<<<dim3((N_BATCH * LQ) / 128, 1), 256>>>(
        query, wa_h, wa_l, b_attn, p_attn, 128);
    // 4) softmax
    softmax16_kernel<<<(NGROUP + 255) / 256, 256>>>(p_attn);
    // 5) deformable sampling
    sample_kernel<<<(N_BATCH * LQ * NH) / 8, 256>>>();
    // 6) output projection [32768, 256]
    gemm_mma_kernel<<<dim3((N_BATCH * LQ) / 128, 2), 256>>>(
        p_sampled, wu_h, wu_l, b_out, out, 256);
}

// round 7
// speedup vs baseline: 1.9968x; 1.4074x over previous
#include <cuda_runtime.h>
#include <cuda_bf16.h>
#include <cuda_fp16.h>
#include <cstdint>
#include <math.h>

// Problem constants (fixed by the reference setup)
#define N_BATCH 2
#define LQ      16384
#define CDIM    256
#define NH      8
#define NL      4
#define NP      4
#define LIN     21760
#define NGROUP  (N_BATCH*LQ*NH)

// Scratch (device globals; allocation is forbidden)
__device__ __half g_value_h[N_BATCH*LIN*CDIM];   // fp16 projected values
__device__ float  g_off    [N_BATCH*LQ*CDIM];
__device__ float  g_attn   [N_BATCH*LQ*NH*NL*NP];
__device__ float  g_sampled[N_BATCH*LQ*CDIM];
// Pre-transposed weights, bf16 hi/lo split: [N, K=256] row-major
__device__ __nv_bfloat16 g_wval_hi [CDIM*CDIM], g_wval_lo [CDIM*CDIM];
__device__ __nv_bfloat16 g_woff_hi [CDIM*CDIM], g_woff_lo [CDIM*CDIM];
__device__ __nv_bfloat16 g_wattn_hi[128*CDIM],  g_wattn_lo[128*CDIM];
__device__ __nv_bfloat16 g_wout_hi [CDIM*CDIM], g_wout_lo [CDIM*CDIM];

// ---------------------------------------------------------------------------
// PTX helpers (baseline PTX only — sm_103 non-variant target)
// ---------------------------------------------------------------------------
__device__ __forceinline__ uint32_t smem_u32(const void* p) {
    uint32_t a;
    asm("{ .reg .u64 t; cvta.to.shared.u64 t, %1; cvt.u32.u64 %0, t; }"
        : "=r"(a) : "l"(p));
    return a;
}
__device__ __forceinline__ void ldsm4(uint32_t* r, uint32_t addr) {
    asm volatile("ldmatrix.sync.aligned.m8n8.x4.shared.b16 {%0,%1,%2,%3}, [%4];"
                 : "=r"(r[0]), "=r"(r[1]), "=r"(r[2]), "=r"(r[3]) : "r"(addr));
}
__device__ __forceinline__ void mma16816(float* d, const uint32_t* a, const uint32_t* b) {
    asm volatile(
        "mma.sync.aligned.m16n8k16.row.col.f32.bf16.bf16.f32 "
        "{%0,%1,%2,%3}, {%4,%5,%6,%7}, {%8,%9}, {%0,%1,%2,%3};"
        : "+f"(d[0]), "+f"(d[1]), "+f"(d[2]), "+f"(d[3])
        : "r"(a[0]), "r"(a[1]), "r"(a[2]), "r"(a[3]), "r"(b[0]), "r"(b[1]));
}
#define CP_ASYNC16(dst, src) \
    asm volatile("cp.async.ca.shared.global [%0], [%1], 16;" :: "r"(dst), "l"(src))
#define CP_COMMIT()  asm volatile("cp.async.commit_group;")
#define CP_WAIT0()   asm volatile("cp.async.wait_group 0;" ::: "memory")

// ---------------------------------------------------------------------------
// Fused weight transpose + bf16 hi/lo split (4 weights, one launch)
// ---------------------------------------------------------------------------
__global__ void transpose_all_kernel(
    const float* __restrict__ Wv, const float* __restrict__ Wo,
    const float* __restrict__ Wa, const float* __restrict__ Wu)
{
    const int which = blockIdx.y;
    const int N = (which == 2) ? 128 : 256;
    int idx = blockIdx.x * 256 + threadIdx.x;
    if (idx >= 256 * N) return;
    const float* W = (which == 0) ? Wv : (which == 1) ? Wo : (which == 2) ? Wa : Wu;
    __nv_bfloat16* hi = (which == 0) ? g_wval_hi : (which == 1) ? g_woff_hi
                       : (which == 2) ? g_wattn_hi : g_wout_hi;
    __nv_bfloat16* lo = (which == 0) ? g_wval_lo : (which == 1) ? g_woff_lo
                       : (which == 2) ? g_wattn_lo : g_wout_lo;
    int k = idx / N, n = idx % N;
    float w = W[idx];
    __nv_bfloat16 h = __float2bfloat16(w);
    hi[n * 256 + k] = h;
    lo[n * 256 + k] = __float2bfloat16(w - __bfloat162float(h));
}

// ---------------------------------------------------------------------------
// HMMA GEMM, bf16x3 split, double-buffered (cp.async for B, reg-prefetch A).
// C[M,N] = A[M,256] @ Bt[N,256]^T + bias. CTA 128x128, BK=32, 8 warps 4x2.
// HALF_OUT: write fp16 (value projection) instead of fp32.
// ---------------------------------------------------------------------------
#define GK       256
#define GBK      32
#define ASTRIDEB 80                    // 64B data + 16B pad per 32-elem row
#define ABUF     (128 * ASTRIDEB)      // 10240 bytes per (stage, hi/lo) tile
#define SMEM_GEMM (8 * ABUF)           // A:2stg x2 + B:2stg x2 = 81920B

template<bool HALF_OUT>
__global__ __launch_bounds__(256, 2) void gemm_mma_kernel(
    const float* __restrict__ A,
    const __nv_bfloat16* __restrict__ Bt_hi,
    const __nv_bfloat16* __restrict__ Bt_lo,
    const float* __restrict__ bias,
    void* __restrict__ Cv, int ldc)
{
    extern __shared__ __align__(16) char sm[];
    // layout: A_hi(s)=s*2*ABUF, A_lo(s)=s*2*ABUF+ABUF,
    //         B_hi(s)=4*ABUF+s*2*ABUF, B_lo(s)=+ABUF
    const uint32_t sb = smem_u32(sm);
    const int tid  = threadIdx.x;
    const int wid  = tid >> 5, lane = tid & 31;
    const int wm   = wid & 3,  wn   = wid >> 2;
    const int m0   = blockIdx.x * 128;
    const int n0   = blockIdx.y * 128;

    const int frow = tid >> 1;
    const int fkh  = (tid & 1) * 16;

    float acc[2][8][4];
    #pragma unroll
    for (int i = 0; i < 2; i++)
        #pragma unroll
        for (int j = 0; j < 8; j++)
            #pragma unroll
            for (int v = 0; v < 4; v++) acc[i][j][v] = 0.f;

    // ldmatrix per-thread source addresses (stage-0 A-region base)
    uint32_t a_addr[2];
    #pragma unroll
    for (int mt = 0; mt < 2; mt++)
        a_addr[mt] = sb + (wm * 32 + mt * 16 + (lane & 15)) * ASTRIDEB
                        + ((lane >> 4) * 8) * 2;
    uint32_t b_addr[4];
    #pragma unroll
    for (int bt = 0; bt < 4; bt++)
        b_addr[bt] = sb + (wn * 64 + bt * 16 + ((lane >> 4) * 8) + (lane & 7)) * ASTRIDEB
                        + (((lane >> 3) & 1) * 8) * 2;

    const float* arow_ptr = A + (size_t)(m0 + frow) * GK + fkh;
    const __nv_bfloat16* bh_ptr = Bt_hi + (size_t)(n0 + frow) * GK + fkh;
    const __nv_bfloat16* bl_ptr = Bt_lo + (size_t)(n0 + frow) * GK + fkh;
    const uint32_t bfill = sb + frow * ASTRIDEB + fkh * 2;   // + region offset

    // prologue: B(0) via cp.async into stage 0; A(0) into registers
    {
        uint32_t dh = bfill + 4 * ABUF;
        uint32_t dl = dh + ABUF;
        CP_ASYNC16(dh,      bh_ptr);
        CP_ASYNC16(dh + 16, bh_ptr + 8);
        CP_ASYNC16(dl,      bl_ptr);
        CP_ASYNC16(dl + 16, bl_ptr + 8);
        CP_COMMIT();
    }
    float4 va[4];
    #pragma unroll
    for (int j = 0; j < 4; j++) va[j] = ((const float4*)arow_ptr)[j];

    for (int i = 0; i < GK / GBK; i++) {
        const int s = i & 1;

        // convert A(i) regs -> bf16 hi/lo smem stage s
        {
            float v[16];
            #pragma unroll
            for (int j = 0; j < 4; j++) {
                v[j*4+0] = va[j].x; v[j*4+1] = va[j].y;
                v[j*4+2] = va[j].z; v[j*4+3] = va[j].w;
            }
            __nv_bfloat16 h[16], l[16];
            #pragma unroll
            for (int j = 0; j < 16; j++) {
                h[j] = __float2bfloat16(v[j]);
                l[j] = __float2bfloat16(v[j] - __bfloat162float(h[j]));
            }
            char* dh = sm + s * 2 * ABUF + frow * ASTRIDEB + fkh * 2;
            char* dl = dh + ABUF;
            ((uint4*)dh)[0] = ((uint4*)h)[0];  ((uint4*)dh)[1] = ((uint4*)h)[1];
            ((uint4*)dl)[0] = ((uint4*)l)[0];  ((uint4*)dl)[1] = ((uint4*)l)[1];
        }
        // prefetch A(i+1) into registers (in flight during compute)
        if (i < GK / GBK - 1) {
            const float4* nxt = (const float4*)(arow_ptr + (i + 1) * GBK);
            #pragma unroll
            for (int j = 0; j < 4; j++) va[j] = nxt[j];
        }

        CP_WAIT0();          // B(i) arrived
        __syncthreads();

        // issue B(i+1) into stage s^1 (overlaps compute below; safe post-sync)
        if (i < GK / GBK - 1) {
            const __nv_bfloat16* sh = bh_ptr + (i + 1) * GBK;
            const __nv_bfloat16* sl = bl_ptr + (i + 1) * GBK;
            uint32_t dh = bfill + 4 * ABUF + (s ^ 1) * 2 * ABUF;
            uint32_t dl = dh + ABUF;
            CP_ASYNC16(dh,      sh);
            CP_ASYNC16(dh + 16, sh + 8);
            CP_ASYNC16(dl,      sl);
            CP_ASYNC16(dl + 16, sl + 8);
            CP_COMMIT();
        }

        const uint32_t aoffS = s * 2 * ABUF;
        const uint32_t boffS = 4 * ABUF + s * 2 * ABUF;
        #pragma unroll
        for (int kk = 0; kk < GBK; kk += 16) {
            const uint32_t ko = kk * 2;
            uint32_t ah[2][4], al[2][4];
            #pragma unroll
            for (int mt = 0; mt < 2; mt++) {
                ldsm4(ah[mt], a_addr[mt] + aoffS + ko);
                ldsm4(al[mt], a_addr[mt] + aoffS + ABUF + ko);
            }
            #pragma unroll
            for (int bt = 0; bt < 4; bt++) {
                uint32_t bh[4], bl[4];
                ldsm4(bh, b_addr[bt] + boffS + ko);
                ldsm4(bl, b_addr[bt] + boffS + ABUF + ko);
                #pragma unroll
                for (int mt = 0; mt < 2; mt++) {
                    float* d0 = acc[mt][bt * 2 + 0];
                    float* d1 = acc[mt][bt * 2 + 1];
                    mma16816(d0, ah[mt], bh + 0);
                    mma16816(d0, ah[mt], bl + 0);
                    mma16816(d0, al[mt], bh + 0);
                    mma16816(d1, ah[mt], bh + 2);
                    mma16816(d1, ah[mt], bl + 2);
                    mma16816(d1, al[mt], bh + 2);
                }
            }
        }
        __syncthreads();
    }

    // epilogue
    const int r_in = lane >> 2;
    const int c_in = (lane & 3) * 2;
    #pragma unroll
    for (int mt = 0; mt < 2; mt++) {
        const int rbase = m0 + wm * 32 + mt * 16 + r_in;
        #pragma unroll
        for (int nf = 0; nf < 8; nf++) {
            const int col = n0 + wn * 64 + nf * 8 + c_in;
            const float b0 = bias[col], b1 = bias[col + 1];
            float* d = acc[mt][nf];
            if (HALF_OUT) {
                __half* C = (__half*)Cv;
                *(__half2*)(C + (size_t)rbase       * ldc + col) =
                    __floats2half2_rn(d[0] + b0, d[1] + b1);
                *(__half2*)(C + (size_t)(rbase + 8) * ldc + col) =
                    __floats2half2_rn(d[2] + b0, d[3] + b1);
            } else {
                float* C = (float*)Cv;
                *(float2*)(C + (size_t)rbase       * ldc + col) = make_float2(d[0] + b0, d[1] + b1);
                *(float2*)(C + (size_t)(rbase + 8) * ldc + col) = make_float2(d[2] + b0, d[3] + b1);
            }
        }
    }
}

// ---------------------------------------------------------------------------
// Softmax over groups of 16 (one thread per (n,q,head))
// ---------------------------------------------------------------------------
__global__ void softmax16_kernel(float* __restrict__ attn)
{
    int i = blockIdx.x * blockDim.x + threadIdx.x;
    if (i >= NGROUP) return;
    float* p = attn + (size_t)i * 16;
    float4 v0 = *(float4*)(p + 0);
    float4 v1 = *(float4*)(p + 4);
    float4 v2 = *(float4*)(p + 8);
    float4 v3 = *(float4*)(p + 12);
    float vals[16] = {v0.x,v0.y,v0.z,v0.w, v1.x,v1.y,v1.z,v1.w,
                      v2.x,v2.y,v2.z,v2.w, v3.x,v3.y,v3.z,v3.w};
    float mx = vals[0];
    #pragma unroll
    for (int k = 1; k < 16; k++) mx = fmaxf(mx, vals[k]);
    float s = 0.f;
    #pragma unroll
    for (int k = 0; k < 16; k++) { vals[k] = expf(vals[k] - mx); s += vals[k]; }
    float inv = 1.f / s;
    #pragma unroll
    for (int k = 0; k < 16; k++) vals[k] *= inv;
    *(float4*)(p + 0)  = make_float4(vals[0],vals[1],vals[2],vals[3]);
    *(float4*)(p + 4)  = make_float4(vals[4],vals[5],vals[6],vals[7]);
    *(float4*)(p + 8)  = make_float4(vals[8],vals[9],vals[10],vals[11]);
    *(float4*)(p + 12) = make_float4(vals[12],vals[13],vals[14],vals[15]);
}

// ---------------------------------------------------------------------------
// Deformable sampling, fp16 values, 2 heads per warp.
// lane = half*16 + d2; half selects head (m = 2*mp + half), d2 -> channels
// 2*d2, 2*d2+1 loaded as __half2. Weight pairing: sample(l,p) uses
// attn[p*4+l] (reference pairs p-major values with l-major weights).
// ---------------------------------------------------------------------------
__global__ __launch_bounds__(256) void sample_kernel()
{
    const int wg   = (blockIdx.x * 256 + threadIdx.x) >> 5;  // (n,q,mp)
    const int lane = threadIdx.x & 31;
    const int mp = wg & 3;
    const int q  = (wg >> 2) & (LQ - 1);
    const int n  = wg >> 16;
    const int m  = mp * 2 + (lane >> 4);
    const int d2 = lane & 15;

    const float refx = ((q & 127) + 0.5f) * (1.0f / 128.0f);
    const float refy = ((q >> 7)  + 0.5f) * (1.0f / 128.0f);

    const float* offp  = g_off  + (size_t)(n * LQ + q) * CDIM + m * (NL * NP * 2);
    const float* attnp = g_attn + (size_t)(n * LQ + q) * (NH * NL * NP) + m * (NL * NP);

    float2 acc = make_float2(0.f, 0.f);
    int start = 0;
    #pragma unroll
    for (int l = 0; l < NL; l++) {
        const int W = 128 >> l;
        const float fW = (float)W;
        const __half* vb = g_value_h + ((size_t)(n * LIN + start)) * CDIM + m * 32 + 2 * d2;

        #pragma unroll
        for (int p = 0; p < NP; p++) {
            const int pi = l * NP + p;
            const float ox = offp[pi * 2 + 0];
            const float oy = offp[pi * 2 + 1];
            const float a  = attnp[p * NP + l];

            const float x = refx * fW + ox - 0.5f;
            const float y = refy * fW + oy - 0.5f;
            const float xf = floorf(x), yf = floorf(y);
            const int x0 = (int)xf, y0 = (int)yf;
            const float wx1 = x - xf, wy1 = y - yf;
            const float wx0 = 1.f - wx1, wy0 = 1.f - wy1;

            const bool vx0 = (x0 >= 0) && (x0 < W);
            const bool vx1 = (x0 >= -1) && (x0 < W - 1);
            const bool vy0 = (y0 >= 0) && (y0 < W);
            const bool vy1 = (y0 >= -1) && (y0 < W - 1);

            const int base0 = y0 * W + x0;
            const __half2 hz = __float2half2_rn(0.f);
            __half2 c00 = (vy0 && vx0) ? *(const __half2*)(vb + (size_t)(base0)         * CDIM) : hz;
            __half2 c01 = (vy0 && vx1) ? *(const __half2*)(vb + (size_t)(base0 + 1)     * CDIM) : hz;
            __half2 c10 = (vy1 && vx0) ? *(const __half2*)(vb + (size_t)(base0 + W)     * CDIM) : hz;
            __half2 c11 = (vy1 && vx1) ? *(const __half2*)(vb + (size_t)(base0 + W + 1) * CDIM) : hz;

            const float w00 = wy0 * wx0, w01 = wy0 * wx1;
            const float w10 = wy1 * wx0, w11 = wy1 * wx1;
            float2 f00 = __half22float2(c00), f01 = __half22float2(c01);
            float2 f10 = __half22float2(c10), f11 = __half22float2(c11);
            acc.x = fmaf(a, w00*f00.x + w01*f01.x + w10*f10.x + w11*f11.x, acc.x);
            acc.y = fmaf(a, w00*f00.y + w01*f01.y + w10*f10.y + w11*f11.y, acc.y);
        }
        start += W * W;
    }
    *(float2*)(g_sampled + (size_t)(n * LQ + q) * CDIM + m * 32 + 2 * d2) = acc;
}

// ---------------------------------------------------------------------------
// kernel_launch
// ---------------------------------------------------------------------------
extern "C" void kernel_launch(void* const* d_in, const int* in_sizes, int n_in,
                              void* d_out, int out_size)
{
    const float* query         = (const float*)d_in[0];
    const float* input_flatten = (const float*)d_in[2];
    const float* W_off  = (const float*)d_in[5];
    const float* b_off  = (const float*)d_in[6];
    const float* W_attn = (const float*)d_in[7];
    const float* b_attn = (const float*)d_in[8];
    const float* W_val  = (const float*)d_in[9];
    const float* b_val  = (const float*)d_in[10];
    const float* W_out  = (const float*)d_in[11];
    const float* b_out  = (const float*)d_in[12];
    float* out = (float*)d_out;

    __half* p_value_h; float *p_off, *p_attn, *p_sampled;
    cudaGetSymbolAddress((void**)&p_value_h, g_value_h);
    cudaGetSymbolAddress((void**)&p_off,     g_off);
    cudaGetSymbolAddress((void**)&p_attn,    g_attn);
    cudaGetSymbolAddress((void**)&p_sampled, g_sampled);
    __nv_bfloat16 *wv_h, *wv_l, *wo_h, *wo_l, *wa_h, *wa_l, *wu_h, *wu_l;
    cudaGetSymbolAddress((void**)&wv_h, g_wval_hi);  cudaGetSymbolAddress((void**)&wv_l, g_wval_lo);
    cudaGetSymbolAddress((void**)&wo_h, g_woff_hi);  cudaGetSymbolAddress((void**)&wo_l, g_woff_lo);
    cudaGetSymbolAddress((void**)&wa_h, g_wattn_hi); cudaGetSymbolAddress((void**)&wa_l, g_wattn_lo);
    cudaGetSymbolAddress((void**)&wu_h, g_wout_hi);  cudaGetSymbolAddress((void**)&wu_l, g_wout_lo);

    cudaFuncSetAttribute(gemm_mma_kernel<false>,
                         cudaFuncAttributeMaxDynamicSharedMemorySize, SMEM_GEMM);
    cudaFuncSetAttribute(gemm_mma_kernel<true>,
                         cudaFuncAttributeMaxDynamicSharedMemorySize, SMEM_GEMM);

    // 0) weight transpose + split (single launch)
    transpose_all_kernel<<<dim3(256, 4), 256>>>(W_val, W_off, W_attn, W_out);

    // 1) value projection [43520, 256] -> fp16
    gemm_mma_kernel<true><<<dim3((N_BATCH * LIN) / 128, 2), 256, SMEM_GEMM>>>(
        input_flatten, wv_h, wv_l, b_val, p_value_h, 256);
    // 2) offset projection [32768, 256]
    gemm_mma_kernel<false><<<dim3((N_BATCH * LQ) / 128, 2), 256, SMEM_GEMM>>>(
        query, wo_h, wo_l, b_off, p_off, 256);
    // 3) attention logits [32768, 128]
    gemm_mma_kernel<false><<<dim3((N_BATCH * LQ) / 128, 1), 256, SMEM_GEMM>>>(
        query, wa_h, wa_l, b_attn, p_attn, 128);
    // 4) softmax
    softmax16_kernel<<<(NGROUP + 255) / 256, 256>>>(p_attn);
    // 5) deformable sampling (fp16 values, 2 heads/warp)
    sample_kernel<<<(N_BATCH * LQ * 4) / 8, 256>>>();
    // 6) output projection [32768, 256]
    gemm_mma_kernel<false><<<dim3((N_BATCH * LQ) / 128, 2), 256, SMEM_GEMM>>>(
        p_sampled, wu_h, wu_l, b_out, out, 256);
}